// round 1
// baseline (speedup 1.0000x reference)
#include <cuda_runtime.h>
#include <cstdint>

#define N_PTS 262144
#define P_PL  128
#define D_F   64
#define EPSV  1e-5f

#define PN ((size_t)P_PL * (size_t)N_PTS)   // 33,554,432

// Scratch (sanctioned: __device__ globals, no runtime allocation)
__device__ float g_h2[N_PTS * D_F];      // 67 MB
__device__ float g_scores[N_PTS];        // 1 MB

// ---------------------------------------------------------------------------
// Kernel 0: zero the on_feat/off_feat output region (d_out is poisoned)
// ---------------------------------------------------------------------------
__global__ void k_init(float* __restrict__ feat_out) {
    int i = blockIdx.x * blockDim.x + threadIdx.x;
    if (i < 2 * P_PL * D_F) feat_out[i] = 0.0f;
}

// ---------------------------------------------------------------------------
// Kernel 1: per-point MLP  (f=[feature|feature_geo] -> h1 -> h2 -> score)
// One thread per point. Weights staged in shared, read as float4 broadcasts.
// ---------------------------------------------------------------------------
__global__ __launch_bounds__(256)
void k_mlp(const float* __restrict__ feature,
           const float* __restrict__ feature_geo,
           const float* __restrict__ w1, const float* __restrict__ b1,
           const float* __restrict__ g1, const float* __restrict__ be1,
           const float* __restrict__ m1, const float* __restrict__ v1,
           const float* __restrict__ w2, const float* __restrict__ b2,
           const float* __restrict__ g2, const float* __restrict__ be2,
           const float* __restrict__ m2, const float* __restrict__ v2,
           const float* __restrict__ w3, const float* __restrict__ b3)
{
    __shared__ float4 w1s[128 * 16];   // [k][d/4]
    __shared__ float4 w2s[64 * 16];    // [k][d/4]
    __shared__ float  s1[64], t1[64], s2[64], t2[64], w3s[64];
    __shared__ float  b3s;

    const int tid = threadIdx.x;
    for (int j = tid; j < 128 * 16; j += 256) w1s[j] = ((const float4*)w1)[j];
    for (int j = tid; j < 64 * 16;  j += 256) w2s[j] = ((const float4*)w2)[j];
    if (tid < 64) {
        float s = g1[tid] * rsqrtf(v1[tid] + EPSV);
        s1[tid] = s;
        t1[tid] = (b1[tid] - m1[tid]) * s + be1[tid];
        s = g2[tid] * rsqrtf(v2[tid] + EPSV);
        s2[tid] = s;
        t2[tid] = (b2[tid] - m2[tid]) * s + be2[tid];
        w3s[tid] = w3[tid];
    }
    if (tid == 0) b3s = b3[0];
    __syncthreads();

    const int i = blockIdx.x * 256 + tid;

    float acc[64];
#pragma unroll
    for (int d = 0; d < 64; d++) acc[d] = 0.0f;

    const float4* fv = (const float4*)feature + (size_t)i * 16;
    const float4* gv = (const float4*)feature_geo + (size_t)i * 16;

    // ---- layer 1: k = 0..63 from feature ----
    for (int q = 0; q < 16; q++) {
        float4 f = fv[q];
        const float4* wrow = &w1s[q * 4 * 16];
#pragma unroll
        for (int kk = 0; kk < 4; kk++) {
            float fk = (kk == 0) ? f.x : (kk == 1) ? f.y : (kk == 2) ? f.z : f.w;
#pragma unroll
            for (int dv = 0; dv < 16; dv++) {
                float4 w = wrow[kk * 16 + dv];
                acc[dv * 4 + 0] = fmaf(fk, w.x, acc[dv * 4 + 0]);
                acc[dv * 4 + 1] = fmaf(fk, w.y, acc[dv * 4 + 1]);
                acc[dv * 4 + 2] = fmaf(fk, w.z, acc[dv * 4 + 2]);
                acc[dv * 4 + 3] = fmaf(fk, w.w, acc[dv * 4 + 3]);
            }
        }
    }
    // ---- layer 1: k = 64..127 from feature_geo ----
    for (int q = 0; q < 16; q++) {
        float4 f = gv[q];
        const float4* wrow = &w1s[(64 + q * 4) * 16];
#pragma unroll
        for (int kk = 0; kk < 4; kk++) {
            float fk = (kk == 0) ? f.x : (kk == 1) ? f.y : (kk == 2) ? f.z : f.w;
#pragma unroll
            for (int dv = 0; dv < 16; dv++) {
                float4 w = wrow[kk * 16 + dv];
                acc[dv * 4 + 0] = fmaf(fk, w.x, acc[dv * 4 + 0]);
                acc[dv * 4 + 1] = fmaf(fk, w.y, acc[dv * 4 + 1]);
                acc[dv * 4 + 2] = fmaf(fk, w.z, acc[dv * 4 + 2]);
                acc[dv * 4 + 3] = fmaf(fk, w.w, acc[dv * 4 + 3]);
            }
        }
    }

    // bn + relu -> h1 held in acc[]
#pragma unroll
    for (int d = 0; d < 64; d++)
        acc[d] = fmaxf(fmaf(acc[d], s1[d], t1[d]), 0.0f);

    // ---- layer 2 (two halves of 32 outputs to cap registers) ----
    float score = b3s;
#pragma unroll
    for (int half = 0; half < 2; half++) {
        float a2[32];
#pragma unroll
        for (int d = 0; d < 32; d++) a2[d] = 0.0f;
#pragma unroll
        for (int k = 0; k < 64; k++) {
            float hk = acc[k];
#pragma unroll
            for (int dv = 0; dv < 8; dv++) {
                float4 w = w2s[k * 16 + half * 8 + dv];
                a2[dv * 4 + 0] = fmaf(hk, w.x, a2[dv * 4 + 0]);
                a2[dv * 4 + 1] = fmaf(hk, w.y, a2[dv * 4 + 1]);
                a2[dv * 4 + 2] = fmaf(hk, w.z, a2[dv * 4 + 2]);
                a2[dv * 4 + 3] = fmaf(hk, w.w, a2[dv * 4 + 3]);
            }
        }
        float4* out4 = (float4*)&g_h2[(size_t)i * 64 + half * 32];
#pragma unroll
        for (int dv = 0; dv < 8; dv++) {
            int d0 = half * 32 + dv * 4;
            float4 o;
            o.x = fmaxf(fmaf(a2[dv * 4 + 0], s2[d0 + 0], t2[d0 + 0]), 0.0f);
            o.y = fmaxf(fmaf(a2[dv * 4 + 1], s2[d0 + 1], t2[d0 + 1]), 0.0f);
            o.z = fmaxf(fmaf(a2[dv * 4 + 2], s2[d0 + 2], t2[d0 + 2]), 0.0f);
            o.w = fmaxf(fmaf(a2[dv * 4 + 3], s2[d0 + 3], t2[d0 + 3]), 0.0f);
            score = fmaf(o.x, w3s[d0 + 0], score);
            score = fmaf(o.y, w3s[d0 + 1], score);
            score = fmaf(o.z, w3s[d0 + 2], score);
            score = fmaf(o.w, w3s[d0 + 3], score);
            out4[dv] = o;
        }
    }
    g_scores[i] = fmaxf(score, 0.0f);
}

// ---------------------------------------------------------------------------
// Kernel 2: masks + 4 big outputs + masked max-pool via ballots
// Grid-stride over 512-point chunks; 512 threads/block; 1 block/SM (smem).
// ---------------------------------------------------------------------------
#define K2_THREADS 512
#define CHUNK 512
#define NCHUNK (N_PTS / CHUNK)   // 512

// dynamic shared layout (floats):
//   hs      [CHUNK*64]         = 32768 f   (h2 chunk cache)
//   sAccOn  [128*64]           =  8192 f
//   sAccOff [128*64]           =  8192 f
//   sbOn    [16*128] u32       =  2048 u32
//   sbOff   [16*128] u32       =  2048 u32
//   spn/spmin/spmax [128*3]    =  384*3 f
//   soff    [128] f, scent[4] f
#define SM_HS      0
#define SM_ACCON   (SM_HS + CHUNK * 64)
#define SM_ACCOFF  (SM_ACCON + 8192)
#define SM_SBON    (SM_ACCOFF + 8192)           // as u32
#define SM_SBOFF   (SM_SBON + 2048)
#define SM_PN      (SM_SBOFF + 2048)
#define SM_PMIN    (SM_PN + 384)
#define SM_PMAX    (SM_PMIN + 384)
#define SM_OFF     (SM_PMAX + 384)
#define SM_CENT    (SM_OFF + 128)
#define SM_TOTALF  (SM_CENT + 4)
#define K2_SMEM_BYTES (SM_TOTALF * 4)

__global__ __launch_bounds__(K2_THREADS)
void k_mask(const float* __restrict__ xyz,
            const float* __restrict__ centers,
            const float* __restrict__ plane_center,
            const float* __restrict__ plane_normal,
            const float* __restrict__ plane_min,
            const float* __restrict__ plane_max,
            float* __restrict__ out)
{
    extern __shared__ float sm[];
    float*    hs     = sm + SM_HS;
    float*    accOn  = sm + SM_ACCON;
    float*    accOff = sm + SM_ACCOFF;
    unsigned* sbOn   = (unsigned*)(sm + SM_SBON);
    unsigned* sbOff  = (unsigned*)(sm + SM_SBOFF);
    float*    spn    = sm + SM_PN;
    float*    spmin  = sm + SM_PMIN;
    float*    spmax  = sm + SM_PMAX;
    float*    soff   = sm + SM_OFF;
    float*    scent  = sm + SM_CENT;

    const int tid  = threadIdx.x;
    const int warp = tid >> 5;
    const int lane = tid & 31;

    for (int j = tid; j < 8192; j += K2_THREADS) { accOn[j] = 0.0f; accOff[j] = 0.0f; }
    for (int j = tid; j < 384; j += K2_THREADS) {
        spn[j] = plane_normal[j]; spmin[j] = plane_min[j]; spmax[j] = plane_max[j];
    }
    if (tid < 128) {
        soff[tid] = plane_center[tid * 3 + 0] * plane_normal[tid * 3 + 0]
                  + plane_center[tid * 3 + 1] * plane_normal[tid * 3 + 1]
                  + plane_center[tid * 3 + 2] * plane_normal[tid * 3 + 2];
    }
    if (tid < 3) scent[tid] = centers[tid];
    __syncthreads();

    float* outS  = out;
    float* outM  = out + PN;
    float* outOn = out + 2 * PN;
    float* outOf = out + 3 * PN;

    const float4* h2v = (const float4*)g_h2;
    float4* hsv = (float4*)hs;

    for (int c = blockIdx.x; c < NCHUNK; c += gridDim.x) {
        const int base = c * CHUNK;
        __syncthreads();   // previous chunk's phase B done before overwrite

        // stage h2 chunk
        for (int j = tid; j < CHUNK * 16; j += K2_THREADS)
            hsv[j] = h2v[(size_t)base * 16 + j];

        const int i = base + tid;
        const float clx = xyz[(size_t)i * 3 + 0] + scent[0];
        const float cly = xyz[(size_t)i * 3 + 1] + scent[1];
        const float clz = xyz[(size_t)i * 3 + 2] + scent[2];
        const float sc  = g_scores[i];
        const bool  pos = sc > 0.0f;

        // phase A: masks, big outputs, ballots
        for (int p = 0; p < 128; p++) {
            const float nx = spn[p * 3 + 0], ny = spn[p * 3 + 1], nz = spn[p * 3 + 2];
            float d = fabsf(clx * nx + cly * ny + clz * nz - soff[p]);
            bool m = d < 0.1f;
            {
                float mn = spmin[p * 3 + 0], mx = spmax[p * 3 + 0];
                m = m && ((mx == 0.0f) || (clx >= mn && clx < mx));
                mn = spmin[p * 3 + 1]; mx = spmax[p * 3 + 1];
                m = m && ((mx == 0.0f) || (cly >= mn && cly < mx));
                mn = spmin[p * 3 + 2]; mx = spmax[p * 3 + 2];
                m = m && ((mx == 0.0f) || (clz >= mn && clz < mx));
            }
            const size_t idx = (size_t)p * N_PTS + i;
            const bool on  = m && pos;
            const bool off = m && !pos;
            outS[idx]  = m   ? sc   : 0.0f;
            outM[idx]  = m   ? 1.0f : 0.0f;
            outOn[idx] = on  ? 1.0f : 0.0f;
            outOf[idx] = off ? 1.0f : 0.0f;
            const unsigned bo = __ballot_sync(0xFFFFFFFFu, on);
            const unsigned bf = __ballot_sync(0xFFFFFFFFu, off);
            if (lane == 0) { sbOn[warp * 128 + p] = bo; sbOff[warp * 128 + p] = bf; }
        }
        __syncthreads();

        // phase B: sparse masked max-pool from shared h2 cache
        const float2* hs2 = (const float2*)hs;
#pragma unroll
        for (int j = 0; j < 8; j++) {
            const int p = warp + j * 16;      // static plane ownership per warp
            float a0 = 0.0f, a1 = 0.0f, f0 = 0.0f, f1 = 0.0f;
            for (int g = 0; g < 16; g++) {
                unsigned bo = sbOn[g * 128 + p];
                while (bo) {
                    const int b = __ffs(bo) - 1; bo &= bo - 1;
                    const float2 v = hs2[(size_t)(g * 32 + b) * 32 + lane];
                    a0 = fmaxf(a0, v.x); a1 = fmaxf(a1, v.y);
                }
                unsigned bf = sbOff[g * 128 + p];
                while (bf) {
                    const int b = __ffs(bf) - 1; bf &= bf - 1;
                    const float2 v = hs2[(size_t)(g * 32 + b) * 32 + lane];
                    f0 = fmaxf(f0, v.x); f1 = fmaxf(f1, v.y);
                }
            }
            float* po = &accOn[p * 64 + lane * 2];
            po[0] = fmaxf(po[0], a0); po[1] = fmaxf(po[1], a1);
            po = &accOff[p * 64 + lane * 2];
            po[0] = fmaxf(po[0], f0); po[1] = fmaxf(po[1], f1);
        }
    }
    __syncthreads();

    // flush (values are >= 0, so int atomicMax == float max; region pre-zeroed)
    float* ofOn = out + 4 * PN;
    float* ofOf = ofOn + P_PL * D_F;
    for (int j = tid; j < P_PL * D_F; j += K2_THREADS) {
        atomicMax((int*)&ofOn[j], __float_as_int(accOn[j]));
        atomicMax((int*)&ofOf[j], __float_as_int(accOff[j]));
    }
}

// ---------------------------------------------------------------------------
// launch
// ---------------------------------------------------------------------------
extern "C" void kernel_launch(void* const* d_in, const int* in_sizes, int n_in,
                              void* d_out, int out_size)
{
    const float* feature      = (const float*)d_in[0];
    const float* feature_geo  = (const float*)d_in[1];
    const float* xyz          = (const float*)d_in[2];
    const float* centers      = (const float*)d_in[3];
    const float* plane_center = (const float*)d_in[4];
    const float* plane_normal = (const float*)d_in[5];
    const float* plane_min    = (const float*)d_in[6];
    const float* plane_max    = (const float*)d_in[7];
    const float* w1 = (const float*)d_in[8];
    const float* b1 = (const float*)d_in[9];
    const float* g1 = (const float*)d_in[10];
    const float* be1 = (const float*)d_in[11];
    const float* m1 = (const float*)d_in[12];
    const float* v1 = (const float*)d_in[13];
    const float* w2 = (const float*)d_in[14];
    const float* b2 = (const float*)d_in[15];
    const float* g2 = (const float*)d_in[16];
    const float* be2 = (const float*)d_in[17];
    const float* m2 = (const float*)d_in[18];
    const float* v2 = (const float*)d_in[19];
    const float* w3 = (const float*)d_in[20];
    const float* b3 = (const float*)d_in[21];

    float* out = (float*)d_out;

    // zero the pooled-feature output region
    k_init<<<(2 * P_PL * D_F + 255) / 256, 256>>>(out + 4 * PN);

    // per-point MLP
    k_mlp<<<N_PTS / 256, 256>>>(feature, feature_geo,
                                w1, b1, g1, be1, m1, v1,
                                w2, b2, g2, be2, m2, v2, w3, b3);

    // masks + outputs + pooling
    static bool attr_set = false;
    if (!attr_set) {
        cudaFuncSetAttribute(k_mask, cudaFuncAttributeMaxDynamicSharedMemorySize,
                             K2_SMEM_BYTES);
        attr_set = true;
    }
    k_mask<<<148, K2_THREADS, K2_SMEM_BYTES>>>(xyz, centers, plane_center,
                                               plane_normal, plane_min, plane_max,
                                               out);
}